// round 15
// baseline (speedup 1.0000x reference)
#include <cuda_runtime.h>
#include <math.h>

// Shapes fixed by dataset: x [2,32,96,96] f32, aff [2,2,4,4] f32,
// out [2,32,96,96,96] f32.
//
// Near-identity affine resampling of a volume that is zero except the
// W=48 plane: ~2% slab of bilinear samples merged into a max-bandwidth
// streaming fill. Measured floor: HBM/LTS write path (~6 TB/s effective).
constexpr int kB   = 2;
constexpr int kC   = 32;
constexpr int kSP  = 96;
constexpr int kNSL = 2;
constexpr int kCS  = kC / kNSL;   // 16
constexpr int kSP2 = kSP * kSP;   // 9216
constexpr int kSP3 = kSP * kSP2;  // 884736
constexpr int kMAXW = 6;          // max slab candidates per row
constexpr int kWIN  = 16;         // per-warp w-window for smem merge
constexpr int kTS   = 17;         // tile row stride (bank-conflict-free)

// ---------------------------------------------------------------------------
// theta = inv( aff * diag(1/zoom,1) )[:3,:]
// ---------------------------------------------------------------------------
__device__ __forceinline__ void compute_theta(const float* __restrict__ A,
                                              float* __restrict__ T) {
    float zoom[3];
#pragma unroll
    for (int j = 0; j < 3; j++) {
        float a0 = A[j], a1 = A[4 + j], a2 = A[8 + j];
        zoom[j] = sqrtf(a0 * a0 + a1 * a1 + a2 * a2);
    }
    float M[3][4];
#pragma unroll
    for (int i = 0; i < 3; i++)
#pragma unroll
        for (int j = 0; j < 4; j++) {
            float v = A[i * 4 + j];
            if (j < 3) v /= zoom[j];
            M[i][j] = v;
        }
    float a = M[0][0], b = M[0][1], c = M[0][2];
    float d = M[1][0], e = M[1][1], f = M[1][2];
    float g = M[2][0], h = M[2][1], i = M[2][2];
    float det = a * (e * i - f * h) - b * (d * i - f * g) + c * (d * h - e * g);
    float id  = 1.0f / det;
    float R00 = (e * i - f * h) * id, R01 = (c * h - b * i) * id, R02 = (b * f - c * e) * id;
    float R10 = (f * g - d * i) * id, R11 = (a * i - c * g) * id, R12 = (c * d - a * f) * id;
    float R20 = (d * h - e * g) * id, R21 = (b * g - a * h) * id, R22 = (a * e - b * d) * id;
    float tx = M[0][3], ty = M[1][3], tz = M[2][3];
    T[0] = R00; T[1] = R01; T[2]  = R02; T[3]  = -(R00 * tx + R01 * ty + R02 * tz);
    T[4] = R10; T[5] = R11; T[6]  = R12; T[7]  = -(R10 * tx + R11 * ty + R12 * tz);
    T[8] = R20; T[9] = R21; T[10] = R22; T[11] = -(R20 * tx + R21 * ty + R22 * tz);
}

// Exact per-voxel sample (identical math to the reference path).
__device__ __forceinline__ float sample_voxel(
    const float* __restrict__ T, const float* __restrict__ xc,
    float gxb, float gyb, float gzb, int w) {
    const float s = 2.0f / kSP;
    float xn = (w + 0.5f) * s - 1.0f;
    float gx = T[0] * xn + gxb;
    float ix = ((gx + 1.0f) * (float)kSP - 1.0f) * 0.5f;
    float fl = floorf(ix);
    float fx = ix - fl;
    float wx = (fl == 48.0f) ? (1.0f - fx) : ((fl == 47.0f) ? fx : 0.0f);
    if (wx <= 0.0f) return 0.0f;

    float gy = T[4] * xn + gyb;
    float gz = T[8] * xn + gzb;
    float iy = ((gy + 1.0f) * (float)kSP - 1.0f) * 0.5f;
    float iz = ((gz + 1.0f) * (float)kSP - 1.0f) * 0.5f;
    float fly = floorf(iy), flz = floorf(iz);
    float fy = iy - fly,    fz = iz - flz;
    int iy0 = (int)fly, iz0 = (int)flz;

    float acc = 0.0f;
#pragma unroll
    for (int k = 0; k < 4; k++) {
        int dy = k & 1, dz = k >> 1;
        int yy = iy0 + dy, zz = iz0 + dz;
        bool v = (yy >= 0) && (yy < kSP) && (zz >= 0) && (zz < kSP);
        float wv = (dz ? fz : 1.0f - fz) * (dy ? fy : 1.0f - fy) * wx;
        int yc = min(max(yy, 0), kSP - 1);
        int zc = min(max(zz, 0), kSP - 1);
        acc += (v ? wv : 0.0f) * __ldg(xc + zc * kSP + yc);
    }
    return acc;
}

// 256-bit streaming store (sm_100+): 8 x b32 with evict-first policy.
__device__ __forceinline__ void stcs_v8(float* __restrict__ p,
                                        const float* __restrict__ v) {
    asm volatile(
        "st.global.cs.v8.b32 [%0], {%1,%2,%3,%4,%5,%6,%7,%8};"
        :: "l"(p),
           "r"(__float_as_uint(v[0])), "r"(__float_as_uint(v[1])),
           "r"(__float_as_uint(v[2])), "r"(__float_as_uint(v[3])),
           "r"(__float_as_uint(v[4])), "r"(__float_as_uint(v[5])),
           "r"(__float_as_uint(v[6])), "r"(__float_as_uint(v[7]))
        : "memory");
}

// ---------------------------------------------------------------------------
// One warp owns 32 consecutive h-rows of one (b,ch,d) slice (12KB contiguous).
//   Phase A: lane L samples its row's slab values into a 32xkWIN smem tile.
//   Phase B: 12 coalesced streaming STG.256 (evict-first); period-3 phase-
//            specialized merge (idx mod 12 = (lane+8i) mod 12) sources the
//            tile only where the warp's slab window overlaps.
//   Fallback (window too wide / degenerate affine): fill + fence + patch.
// ---------------------------------------------------------------------------
__global__ void __launch_bounds__(256, 8) skip_fused(
    const float* __restrict__ x, const float* __restrict__ aff,
    float* __restrict__ out) {

    int wid  = threadIdx.x >> 5;
    int lane = threadIdx.x & 31;
    int warp = blockIdx.x * 8 + wid;

    int hg   = warp % 3;          // h-group: h0 = hg*32
    int rest = warp / 3;
    int c    = rest % kCS;
    rest    /= kCS;
    int d    = rest % kSP;
    int bs   = rest / kSP;        // b*kNSL + sl
    int b    = bs >> 1;
    int sl   = bs & 1;

    __shared__ float T[12];
    __shared__ float tile[8][32 * kTS];
    if (threadIdx.x == 0)
        compute_theta(aff + (sl * kB + b) * 16, T);
    __syncthreads();

    int ch_global = b * kC + sl * kCS + c;
    int h0 = hg * 32;
    size_t base = (size_t)ch_global * kSP3 + (size_t)d * kSP2 + (size_t)h0 * kSP;
    const float* xc = x + (size_t)ch_global * kSP2;

    // ---- Per-lane row geometry (row h = h0 + lane) ----
    int h = h0 + lane;
    const float s = 2.0f / kSP;
    float yn = (h + 0.5f) * s - 1.0f;
    float zn = (d + 0.5f) * s - 1.0f;

    float gxb = T[1] * yn + T[2]  * zn + T[3];
    float gyb = T[5] * yn + T[6]  * zn + T[7];
    float gzb = T[9] * yn + T[10] * zn + T[11];

    // ix(w) = c1*w + c0, hit slab when ix in (47,49)
    float c1 = 48.0f * T[0] * s;
    float c0 = 48.0f * (T[0] * (0.5f * s - 1.0f) + gxb) + 47.5f;

    int wlo = 1, whi = 0;             // empty
    bool fallback = false;
    if (fabsf(c1) < 1e-7f) {
        if (c0 > 47.0f && c0 < 49.0f) { wlo = 0; whi = kSP - 1; fallback = true; }
    } else {
        float wa = (47.0f - c0) / c1;
        float wb = (49.0f - c0) / c1;
        float lo = fminf(wa, wb), hi = fmaxf(wa, wb);
        int l = max(0,       (int)floorf(lo) - 1);
        int r = min(kSP - 1, (int)floorf(hi) + 1);
        if (l <= r) {
            wlo = l; whi = r;
            if (r - l + 1 > kMAXW) fallback = true;
        }
    }
    bool empty = (wlo > whi);

    // ---- Warp aggregates: window + fallback decision ----
    const unsigned FULL = 0xffffffffu;
    int wmin = __reduce_min_sync(FULL, empty ? 0x7fffffff : wlo);
    int wmax = __reduce_max_sync(FULL, empty ? (int)0x80000000 : whi);
    bool have    = (wmin <= wmax);
    bool warp_fb = __any_sync(FULL, fallback) ||
                   (have && (wmax - wmin + 1 > kWIN));

    float* ob = out + base;

    if (!warp_fb) {
        int wbase = have ? wmin : (1 << 20);   // sentinel -> no phase overlaps

        // ---- Phase A: stage samples straight into the tile ----
        float* trow = &tile[wid][lane * kTS];
#pragma unroll
        for (int j = 0; j < kWIN; j++) trow[j] = 0.0f;
        if (!empty) {
#pragma unroll
            for (int j = 0; j < kMAXW; j++) {
                int w = wlo + j;
                if (w <= whi)
                    trow[w - wbase] = sample_voxel(T, xc, gxb, gyb, gzb, w);
            }
        }
        __syncwarp();

        // ---- Phase B: 12 STG.256, period-3 phase specialization ----
        // idx = i*32+lane (float8 units); col8 = idx%12; row = idx/12;
        // w0 = col8*8. (lane + 8i) mod 12 has period 3 in i.
        int  k0p[3];
        int  mkp[3];   // 8-bit validity masks
#pragma unroll
        for (int p = 0; p < 3; p++) {
            int col = lane + 8 * p;
            col -= (col / 12) * 12;            // col mod 12 (compile-time div)
            int k0 = col * 8 - wbase;
            int mask = 0;
#pragma unroll
            for (int j = 0; j < 8; j++)
                if (k0 + j >= 0 && k0 + j < kWIN) mask |= (1 << j);
            k0p[p] = k0; mkp[p] = mask;
        }

        const float* tb = &tile[wid][0];
        int r = lane / 12;                     // row for i=0 (idx=lane)
        int m = lane - r * 12;                 // idx % 12
#pragma unroll
        for (int i = 0; i < 12; i++) {
            int p = i - (i / 3) * 3;           // i % 3, folds at compile time
            float v[8] = {0.f, 0.f, 0.f, 0.f, 0.f, 0.f, 0.f, 0.f};
            if (mkp[p]) {
                const float* tr = tb + r * kTS + k0p[p];
#pragma unroll
                for (int j = 0; j < 8; j++)
                    if (mkp[p] & (1 << j)) v[j] = tr[j];
            }
            stcs_v8(ob + (size_t)(i * 32 + lane) * 8, v);
            m += 8; r += 2;
            if (m >= 12) { m -= 12; r += 1; }
        }
    } else {
        // ---- Fallback: fill + fence + patch (recompute samples) ----
        float4* o4 = reinterpret_cast<float4*>(ob);
        float4 z = make_float4(0.f, 0.f, 0.f, 0.f);
#pragma unroll
        for (int i = 0; i < 24; i++)
            __stcs(o4 + i * 32 + lane, z);
        __threadfence_block();
        __syncwarp();

        float* orow = ob + (size_t)lane * kSP;
        for (int w = wlo; w <= whi; w++) {
            float v = sample_voxel(T, xc, gxb, gyb, gzb, w);
            if (v != 0.0f) orow[w] = v;
        }
    }
}

extern "C" void kernel_launch(void* const* d_in, const int* in_sizes, int n_in,
                              void* d_out, int out_size) {
    const float* x   = (const float*)d_in[0];
    const float* aff = (const float*)d_in[1];
    float* out       = (float*)d_out;

    // warps = kNSL*kB * kSP(d) * kCS(c) * 3(h-groups) = 18432 -> 2304 blocks
    const int warps = kNSL * kB * kSP * kCS * 3;
    skip_fused<<<warps / 8, 256>>>(x, aff, out);
}